// round 5
// baseline (speedup 1.0000x reference)
#include <cuda_runtime.h>
#include <cuda_fp16.h>
#include <stdint.h>
#include <math.h>

#define N      8192
#define FIN    256
#define FOUT   128
#define MT     128
#define KC     64
#define KSLICE 4096
#define NC     64

// smem layout (bytes)
#define OFF_S2 0
#define OFF_EP 16384
#define OFF_EN 32768
#define OFF_RC 49152            // 128 x float4
#define A_STG  18432            // 128 rows x 144B
#define OFF_A  51200            // 2 stages
#define B_STG  18432
#define OFF_B  88064            // 3 stages
#define SMEM_TOTAL (OFF_B + 3 * B_STG)   // 143360

__device__ float g_Wh[(size_t)N * FOUT];
__device__ __half g_WhT[(size_t)FOUT * N];
__device__ float g_s1[N], g_s2[N];
__device__ float g_E2p[N], g_E2n[N];
__device__ float4 g_rc4[N];          // {-s1, r1p, r1n, 0}
__device__ float g_s2max;
__device__ float g_part[2][(size_t)N * FOUT];
__device__ float g_Zpart[2][N];

__device__ __forceinline__ uint32_t smem_u32(const void* p) {
    uint32_t a;
    asm("{ .reg .u64 t; cvta.to.shared.u64 t, %1; cvt.u32.u64 %0, t; }" : "=r"(a) : "l"(p));
    return a;
}
__device__ __forceinline__ void cpa16(uint32_t s, const void* g) {
    asm volatile("cp.async.cg.shared.global [%0], [%1], 16;" :: "r"(s), "l"(g));
}
#define CP_COMMIT() asm volatile("cp.async.commit_group;" ::: "memory")
#define CP_WAIT0()  asm volatile("cp.async.wait_group 0;" ::: "memory")
#define CP_WAIT1()  asm volatile("cp.async.wait_group 1;" ::: "memory")
#define BAR_SYNC(id, n)   asm volatile("bar.sync %0, %1;"   :: "r"(id), "r"(n) : "memory")
#define BAR_ARRIVE(id, n) asm volatile("bar.arrive %0, %1;" :: "r"(id), "r"(n) : "memory")

__device__ __forceinline__ void ldsm4(uint32_t* r, uint32_t addr) {
    asm volatile("ldmatrix.sync.aligned.m8n8.x4.shared.b16 {%0,%1,%2,%3}, [%4];"
        : "=r"(r[0]), "=r"(r[1]), "=r"(r[2]), "=r"(r[3]) : "r"(addr));
}
__device__ __forceinline__ void mma16816(float* d, const uint32_t* a, const uint32_t* b) {
    asm volatile("mma.sync.aligned.m16n8k16.row.col.f32.f16.f16.f32 "
        "{%0,%1,%2,%3}, {%4,%5,%6,%7}, {%8,%9}, {%0,%1,%2,%3};"
        : "+f"(d[0]), "+f"(d[1]), "+f"(d[2]), "+f"(d[3])
        : "r"(a[0]), "r"(a[1]), "r"(a[2]), "r"(a[3]), "r"(b[0]), "r"(b[1]));
}

// ---- Wh = h @ W^T (fp32) + transposed fp16 copy ----
__global__ void __launch_bounds__(128) k_wh(const float* __restrict__ h,
                                            const float* __restrict__ W) {
    __shared__ float hs[32][FIN];
    const int row0 = blockIdx.x * 32, t = threadIdx.x;
    const float4* h4 = (const float4*)(h + (size_t)row0 * FIN);
    float4* hs4 = (float4*)&hs[0][0];
    #pragma unroll
    for (int u = 0; u < 16; u++) hs4[t + u * 128] = h4[t + u * 128];
    __syncthreads();
    const float4* W4 = (const float4*)(W + (size_t)t * FIN);
    float acc[32];
    #pragma unroll
    for (int r = 0; r < 32; r++) acc[r] = 0.f;
    for (int k0 = 0; k0 < FIN; k0 += 32) {
        float4 wv[8];
        #pragma unroll
        for (int c = 0; c < 8; c++) wv[c] = W4[k0 / 4 + c];
        #pragma unroll
        for (int r = 0; r < 32; r++) {
            const float4* hv4 = (const float4*)&hs[r][k0];
            #pragma unroll
            for (int c = 0; c < 8; c++) {
                float4 hv = hv4[c];
                acc[r] += hv.x * wv[c].x; acc[r] += hv.y * wv[c].y;
                acc[r] += hv.z * wv[c].z; acc[r] += hv.w * wv[c].w;
            }
        }
    }
    #pragma unroll
    for (int r = 0; r < 32; r++) {
        g_Wh[(size_t)(row0 + r) * FOUT + t] = acc[r];
        g_WhT[(size_t)t * N + row0 + r] = __float2half_rn(acc[r]);
    }
}

__global__ void __launch_bounds__(256) k_s12(const float* __restrict__ a1,
                                             const float* __restrict__ a2) {
    const int gw = (blockIdx.x * 256 + threadIdx.x) >> 5, lane = threadIdx.x & 31;
    const float* whr = g_Wh + (size_t)gw * FOUT;
    float p1 = 0.f, p2 = 0.f;
    #pragma unroll
    for (int c = 0; c < 4; c++) {
        float v = whr[lane + 32 * c];
        p1 += v * __ldg(&a1[lane + 32 * c]);
        p2 += v * __ldg(&a2[lane + 32 * c]);
    }
    #pragma unroll
    for (int o = 16; o > 0; o >>= 1) {
        p1 += __shfl_xor_sync(~0u, p1, o); p2 += __shfl_xor_sync(~0u, p2, o);
    }
    if (lane == 0) { g_s1[gw] = p1; g_s2[gw] = p2; }
}

__global__ void __launch_bounds__(1024) k_s2max() {
    __shared__ float red[1024];
    const int t = threadIdx.x;
    float m = -1e30f;
    for (int i = t; i < N; i += 1024) m = fmaxf(m, g_s2[i]);
    red[t] = m; __syncthreads();
    for (int s = 512; s > 0; s >>= 1) {
        if (t < s) red[t] = fmaxf(red[t], red[t + s]);
        __syncthreads();
    }
    if (t == 0) g_s2max = red[0];
}

__global__ void __launch_bounds__(256) k_factors() {
    const int i = blockIdx.x * 256 + threadIdx.x;
    const float s1 = g_s1[i], s2 = g_s2[i];
    const float tt = s1 + g_s2max;
    const float c = (tt > 0.f ? tt : 0.2f * tt) - 6.9314718f;
    g_rc4[i] = make_float4(-s1, expf(s1 - c), expf(0.2f * s1 - c), 0.f);
    g_E2p[i] = expf(s2);
    g_E2n[i] = expf(0.2f * s2);
}

// ---- warp-specialized fused masked-softmax attention GEMM ----
__global__ void __launch_bounds__(256, 1) k_attn(const int* __restrict__ adj) {
    extern __shared__ char smem[];
    const uint32_t sb = smem_u32(smem);
    const int t = threadIdx.x, wid = t >> 5, lane = t & 31;
    const int mt_ = blockIdx.x >> 1, slice = blockIdx.x & 1;
    const int row0 = mt_ * MT, jbase = slice * KSLICE;

    if (t < 128) {
        // =================== PRODUCERS (warps 0-3) ===================
        const int pid = t;
        const int wrow = (wid) * 32 + (lane >> 4);   // base row (step 2)
        const int jcol = (lane & 15) * 4;

        // prologue: factor/rc cp.asyncs + adj c=0 LDG
        for (int i = pid; i < 1024; i += 128) {
            cpa16(sb + OFF_S2 + i * 16, g_s2 + jbase + i * 4);
            cpa16(sb + OFF_EP + i * 16, g_E2p + jbase + i * 4);
            cpa16(sb + OFF_EN + i * 16, g_E2n + jbase + i * 4);
        }
        cpa16(sb + OFF_RC + pid * 16, g_rc4 + row0 + pid);
        CP_COMMIT();

        int4 bufA[16], bufB[16];
        {
            const char* base = (const char*)(adj + (size_t)(row0 + wrow) * N + jbase + jcol);
            #pragma unroll
            for (int q = 0; q < 16; q++)
                bufA[q] = __ldg((const int4*)(base + (size_t)q * (2u * N * 4u)));
        }
        CP_WAIT0();
        __syncthreads();

        #pragma unroll 1
        for (int cc = 0; cc < NC; cc += 2) {
            #pragma unroll
            for (int half = 0; half < 2; half++) {
                const int c = cc + half;
                int4* cur = half ? bufB : bufA;
                int4* nxt = half ? bufA : bufB;
                if (c + 1 < NC) {
                    const char* base = (const char*)(adj + (size_t)(row0 + wrow) * N
                                                     + jbase + (c + 1) * KC + jcol);
                    #pragma unroll
                    for (int q = 0; q < 16; q++)
                        nxt[q] = __ldg((const int4*)(base + (size_t)q * (2u * N * 4u)));
                }
                if (c >= 2) BAR_SYNC(3 + (c & 1), 256);

                const int jj = (c * KC + jcol) * 4;
                const float4 sv = *(const float4*)(smem + OFF_S2 + jj);
                const float4 ep = *(const float4*)(smem + OFF_EP + jj);
                const float4 en = *(const float4*)(smem + OFF_EN + jj);
                char* const ab = smem + OFF_A + (c & 1) * A_STG + jcol * 2;
                #pragma unroll
                for (int q = 0; q < 16; q++) {
                    const int rl = wrow + 2 * q;
                    const float4 rc = *(const float4*)(smem + OFF_RC + rl * 16);
                    const int4 a4 = cur[q];
                    float w0 = (sv.x >= rc.x) ? rc.y * ep.x : rc.z * en.x; if (a4.x == 0) w0 = 0.f;
                    float w1 = (sv.y >= rc.x) ? rc.y * ep.y : rc.z * en.y; if (a4.y == 0) w1 = 0.f;
                    float w2 = (sv.z >= rc.x) ? rc.y * ep.z : rc.z * en.z; if (a4.z == 0) w2 = 0.f;
                    float w3 = (sv.w >= rc.x) ? rc.y * ep.w : rc.z * en.w; if (a4.w == 0) w3 = 0.f;
                    __half2 p0 = __floats2half2_rn(w0, w1), p1 = __floats2half2_rn(w2, w3);
                    *(uint2*)(ab + rl * 144) = make_uint2(*(uint32_t*)&p0, *(uint32_t*)&p1);
                }
                BAR_ARRIVE(1 + (c & 1), 256);
            }
        }
    } else {
        // =================== CONSUMERS (warps 4-7) ===================
        const int ct = t - 128;
        const int cw = wid - 4, mi = cw >> 1, ni = cw & 1;

        auto fillB = [&](int c, int s) {
            const __half* src = g_WhT + (size_t)ct * N + jbase + c * KC;
            const uint32_t dst = sb + OFF_B + s * B_STG + ct * 144;
            #pragma unroll
            for (int jc = 0; jc < 8; jc++) cpa16(dst + jc * 16, src + jc * 8);
        };
        fillB(0, 0); CP_COMMIT();
        fillB(1, 1); CP_COMMIT();
        __syncthreads();

        const uint32_t aB0 = sb + OFF_A + (mi * 64 + (lane & 15)) * 144 + (lane >> 4) * 16;
        const uint32_t bOff = (uint32_t)((ni * 64 + (lane & 7) + ((lane >> 4) & 1) * 8) * 144
                                         + ((lane >> 3) & 1) * 16);
        const uint32_t ones[2] = { 0x3C003C00u, 0x3C003C00u };

        float acc[4][8][4];
        float az[4][4];
        #pragma unroll
        for (int i = 0; i < 4; i++) {
            #pragma unroll
            for (int j = 0; j < 8; j++)
                #pragma unroll
                for (int q = 0; q < 4; q++) acc[i][j][q] = 0.f;
            #pragma unroll
            for (int q = 0; q < 4; q++) az[i][q] = 0.f;
        }

        #pragma unroll 1
        for (int c = 0; c < NC; c++) {
            BAR_SYNC(1 + (c & 1), 256);     // A[c&1] full
            CP_WAIT1();                     // own B chunks for iter c done
            BAR_SYNC(5, 128);               // publish B across consumers
            if (c + 2 < NC) fillB(c + 2, (c + 2) % 3);
            CP_COMMIT();

            const uint32_t aB = aB0 + (c & 1) * A_STG;
            const uint32_t bB = sb + OFF_B + (c % 3) * B_STG + bOff;
            #pragma unroll
            for (int kk = 0; kk < 4; kk++) {
                uint32_t a[4][4];
                #pragma unroll
                for (int m4 = 0; m4 < 4; m4++)
                    ldsm4(a[m4], aB + m4 * 16 * 144 + kk * 32);
                #pragma unroll
                for (int ng = 0; ng < 4; ng++) {
                    uint32_t b[4];
                    ldsm4(b, bB + ng * 16 * 144 + kk * 32);
                    #pragma unroll
                    for (int m4 = 0; m4 < 4; m4++) {
                        mma16816(acc[m4][2 * ng], a[m4], b);
                        mma16816(acc[m4][2 * ng + 1], a[m4], b + 2);
                    }
                }
                if (ni == 0) {
                    #pragma unroll
                    for (int m4 = 0; m4 < 4; m4++) mma16816(az[m4], a[m4], ones);
                }
            }
            BAR_ARRIVE(3 + (c & 1), 256);   // A[c&1] empty
        }

        // epilogue
        const int quad = lane >> 2, qc = (lane & 3) * 2;
        #pragma unroll
        for (int m4 = 0; m4 < 4; m4++) {
            const int rg = row0 + mi * 64 + m4 * 16 + quad;
            #pragma unroll
            for (int nt = 0; nt < 8; nt++) {
                const int col = ni * 64 + nt * 8 + qc;
                float* p = g_part[slice] + (size_t)rg * FOUT + col;
                *(float2*)p = make_float2(acc[m4][nt][0], acc[m4][nt][1]);
                *(float2*)(p + 8 * FOUT) = make_float2(acc[m4][nt][2], acc[m4][nt][3]);
            }
            if (ni == 0 && (lane & 3) == 0) {
                g_Zpart[slice][rg] = az[m4][0];
                g_Zpart[slice][rg + 8] = az[m4][2];
            }
        }
    }
}

// combine K-slices: out = elu((p0+p1)/(z0+z1))
__global__ void __launch_bounds__(256) k_final(float* __restrict__ out) {
    const int idx = blockIdx.x * 256 + threadIdx.x;
    const int row = idx >> 5, c4 = (idx & 31) * 4;
    const float4 p0 = *(const float4*)(g_part[0] + (size_t)row * FOUT + c4);
    const float4 p1 = *(const float4*)(g_part[1] + (size_t)row * FOUT + c4);
    const float inv = 1.0f / (g_Zpart[0][row] + g_Zpart[1][row]);
    float4 o; float v;
    v = (p0.x + p1.x) * inv; o.x = v > 0.f ? v : expm1f(v);
    v = (p0.y + p1.y) * inv; o.y = v > 0.f ? v : expm1f(v);
    v = (p0.z + p1.z) * inv; o.z = v > 0.f ? v : expm1f(v);
    v = (p0.w + p1.w) * inv; o.w = v > 0.f ? v : expm1f(v);
    *(float4*)(out + (size_t)row * FOUT + c4) = o;
}

extern "C" void kernel_launch(void* const* d_in, const int* in_sizes, int n_in,
                              void* d_out, int out_size) {
    const float* h   = (const float*)d_in[0];
    const int*   adj = (const int*)d_in[1];
    const float* W   = (const float*)d_in[2];
    const float* a1  = (const float*)d_in[3];
    const float* a2  = (const float*)d_in[4];
    float* out = (float*)d_out;

    cudaFuncSetAttribute(k_attn, cudaFuncAttributeMaxDynamicSharedMemorySize, SMEM_TOTAL);

    k_wh     <<<N / 32, 128>>>(h, W);
    k_s12    <<<N / 8, 256>>>(a1, a2);
    k_s2max  <<<1, 1024>>>();
    k_factors<<<N / 256, 256>>>();
    k_attn   <<<128, 256, SMEM_TOTAL>>>(adj);
    k_final  <<<N * FOUT / 1024, 256>>>(out);
}

// round 6
// speedup vs baseline: 1.0459x; 1.0459x over previous
#include <cuda_runtime.h>
#include <cuda_fp16.h>
#include <stdint.h>
#include <math.h>

#define N      8192
#define FIN    256
#define FOUT   128
#define MT     128
#define KC     64
#define KSLICE 4096
#define NC     64

// smem layout (bytes)
#define OFF_S2  0
#define OFF_EP  16384
#define OFF_EN  32768
#define A_STG   18432           // 128 rows x 144B
#define OFF_A   49152           // 2 stages -> 86016
#define B_STG   18432
#define OFF_B   86016           // 3 stages -> 141312
#define ADJ_STG 34816           // 128 rows x 272B
#define OFF_ADJ 141312          // 2 stages -> 210944
#define SMEM_TOTAL 210944

__device__ float g_Wh[(size_t)N * FOUT];
__device__ __half g_WhT[(size_t)FOUT * N];
__device__ float g_s1[N], g_s2[N];
__device__ float g_E2p[N], g_E2n[N];
__device__ float4 g_rc4[N];          // {-s1, r1p, r1n, 0}
__device__ float g_s2max;
__device__ float g_part[2][(size_t)N * FOUT];
__device__ float g_Zpart[2][N];

__device__ __forceinline__ uint32_t smem_u32(const void* p) {
    uint32_t a;
    asm("{ .reg .u64 t; cvta.to.shared.u64 t, %1; cvt.u32.u64 %0, t; }" : "=r"(a) : "l"(p));
    return a;
}
__device__ __forceinline__ void cpa16(uint32_t s, const void* g) {
    asm volatile("cp.async.cg.shared.global [%0], [%1], 16;" :: "r"(s), "l"(g));
}
#define CP_COMMIT() asm volatile("cp.async.commit_group;" ::: "memory")
#define CP_WAIT0()  asm volatile("cp.async.wait_group 0;" ::: "memory")
#define CP_WAIT1()  asm volatile("cp.async.wait_group 1;" ::: "memory")

__device__ __forceinline__ void ldsm4(uint32_t* r, uint32_t addr) {
    asm volatile("ldmatrix.sync.aligned.m8n8.x4.shared.b16 {%0,%1,%2,%3}, [%4];"
        : "=r"(r[0]), "=r"(r[1]), "=r"(r[2]), "=r"(r[3]) : "r"(addr));
}
__device__ __forceinline__ void mma16816(float* d, const uint32_t* a, const uint32_t* b) {
    asm volatile("mma.sync.aligned.m16n8k16.row.col.f32.f16.f16.f32 "
        "{%0,%1,%2,%3}, {%4,%5,%6,%7}, {%8,%9}, {%0,%1,%2,%3};"
        : "+f"(d[0]), "+f"(d[1]), "+f"(d[2]), "+f"(d[3])
        : "r"(a[0]), "r"(a[1]), "r"(a[2]), "r"(a[3]), "r"(b[0]), "r"(b[1]));
}

// ---- Wh = h @ W^T (fp32) + transposed fp16 copy ----
__global__ void __launch_bounds__(128) k_wh(const float* __restrict__ h,
                                            const float* __restrict__ W) {
    __shared__ float hs[32][FIN];
    const int row0 = blockIdx.x * 32, t = threadIdx.x;
    const float4* h4 = (const float4*)(h + (size_t)row0 * FIN);
    float4* hs4 = (float4*)&hs[0][0];
    #pragma unroll
    for (int u = 0; u < 16; u++) hs4[t + u * 128] = h4[t + u * 128];
    __syncthreads();
    const float4* W4 = (const float4*)(W + (size_t)t * FIN);
    float acc[32];
    #pragma unroll
    for (int r = 0; r < 32; r++) acc[r] = 0.f;
    for (int k0 = 0; k0 < FIN; k0 += 32) {
        float4 wv[8];
        #pragma unroll
        for (int c = 0; c < 8; c++) wv[c] = W4[k0 / 4 + c];
        #pragma unroll
        for (int r = 0; r < 32; r++) {
            const float4* hv4 = (const float4*)&hs[r][k0];
            #pragma unroll
            for (int c = 0; c < 8; c++) {
                float4 hv = hv4[c];
                acc[r] += hv.x * wv[c].x; acc[r] += hv.y * wv[c].y;
                acc[r] += hv.z * wv[c].z; acc[r] += hv.w * wv[c].w;
            }
        }
    }
    #pragma unroll
    for (int r = 0; r < 32; r++) {
        g_Wh[(size_t)(row0 + r) * FOUT + t] = acc[r];
        g_WhT[(size_t)t * N + row0 + r] = __float2half_rn(acc[r]);
    }
}

__global__ void __launch_bounds__(256) k_s12(const float* __restrict__ a1,
                                             const float* __restrict__ a2) {
    const int gw = (blockIdx.x * 256 + threadIdx.x) >> 5, lane = threadIdx.x & 31;
    const float* whr = g_Wh + (size_t)gw * FOUT;
    float p1 = 0.f, p2 = 0.f;
    #pragma unroll
    for (int c = 0; c < 4; c++) {
        float v = whr[lane + 32 * c];
        p1 += v * __ldg(&a1[lane + 32 * c]);
        p2 += v * __ldg(&a2[lane + 32 * c]);
    }
    #pragma unroll
    for (int o = 16; o > 0; o >>= 1) {
        p1 += __shfl_xor_sync(~0u, p1, o); p2 += __shfl_xor_sync(~0u, p2, o);
    }
    if (lane == 0) { g_s1[gw] = p1; g_s2[gw] = p2; }
}

__global__ void __launch_bounds__(1024) k_s2max() {
    __shared__ float red[1024];
    const int t = threadIdx.x;
    float m = -1e30f;
    for (int i = t; i < N; i += 1024) m = fmaxf(m, g_s2[i]);
    red[t] = m; __syncthreads();
    for (int s = 512; s > 0; s >>= 1) {
        if (t < s) red[t] = fmaxf(red[t], red[t + s]);
        __syncthreads();
    }
    if (t == 0) g_s2max = red[0];
}

__global__ void __launch_bounds__(256) k_factors() {
    const int i = blockIdx.x * 256 + threadIdx.x;
    const float s1 = g_s1[i], s2 = g_s2[i];
    const float tt = s1 + g_s2max;
    const float c = (tt > 0.f ? tt : 0.2f * tt) - 6.9314718f;
    g_rc4[i] = make_float4(-s1, expf(s1 - c), expf(0.2f * s1 - c), 0.f);
    g_E2p[i] = expf(s2);
    g_E2n[i] = expf(0.2f * s2);
}

// ---- fused masked-softmax attention GEMM, software-pipelined monolith ----
__global__ void __launch_bounds__(256, 1) k_attn(const int* __restrict__ adj) {
    extern __shared__ char smem[];
    const uint32_t sb = smem_u32(smem);
    const int t = threadIdx.x, wid = t >> 5, lane = t & 31;
    const int mt_ = blockIdx.x >> 1, slice = blockIdx.x & 1;
    const int row0 = mt_ * MT, jbase = slice * KSLICE;

    auto fill_adj = [&](int c, int s) {
        const size_t gcol = (size_t)jbase + (size_t)c * KC;
        #pragma unroll
        for (int k = 0; k < 8; k++) {
            const int id = t + k * 256;
            const int r = id >> 4, cc = id & 15;
            cpa16(sb + OFF_ADJ + s * ADJ_STG + r * 272 + cc * 16,
                  adj + (size_t)(row0 + r) * N + gcol + cc * 4);
        }
    };
    auto fill_B = [&](int c, int s) {
        const size_t gcol = (size_t)jbase + (size_t)c * KC;
        #pragma unroll
        for (int k = 0; k < 4; k++) {
            const int id = t + k * 256;
            const int f = id >> 3, cc = id & 7;
            cpa16(sb + OFF_B + s * B_STG + f * 144 + cc * 16,
                  g_WhT + (size_t)f * N + gcol + cc * 8);
        }
    };

    // gen mapping: one row per thread pair, 32 j's each
    const int m = t >> 1, jh = (t & 1) * 32;
    const float4 rc = __ldg(&g_rc4[row0 + m]);     // {-s1, r1p, r1n}

    // prologue: factors + stages 0,1
    {
        #pragma unroll
        for (int k = 0; k < 4; k++) {
            const int ch = t + k * 256;
            cpa16(sb + OFF_S2 + ch * 16, g_s2 + jbase + ch * 4);
            cpa16(sb + OFF_EP + ch * 16, g_E2p + jbase + ch * 4);
            cpa16(sb + OFF_EN + ch * 16, g_E2n + jbase + ch * 4);
        }
        fill_adj(0, 0); fill_B(0, 0); CP_COMMIT();
        fill_adj(1, 1); fill_B(1, 1); CP_COMMIT();
    }

    // mma mapping: 8 warps = 4x2, warp tile 32 x 64
    const int r0 = (wid >> 1) * 32, c0 = (wid & 1) * 64;
    const uint32_t aB0 = sb + OFF_A + (r0 + (lane & 15)) * 144 + (lane >> 4) * 16;
    const uint32_t bOff = (uint32_t)((c0 + (lane & 7) + ((lane >> 4) & 1) * 8) * 144
                                     + ((lane >> 3) & 1) * 16);
    const uint32_t ones[2] = { 0x3C003C00u, 0x3C003C00u };
    float acc[2][8][4], az[2][4];
    #pragma unroll
    for (int i = 0; i < 2; i++) {
        #pragma unroll
        for (int j = 0; j < 8; j++)
            #pragma unroll
            for (int q = 0; q < 4; q++) acc[i][j][q] = 0.f;
        #pragma unroll
        for (int q = 0; q < 4; q++) az[i][q] = 0.f;
    }

    // gen for one chunk into A[stage]
    auto gen = [&](int c) {
        const int s = c & 1;
        const int4* ar = (const int4*)(smem + OFF_ADJ + s * ADJ_STG + m * 272 + jh * 4);
        const float4* s2p = (const float4*)(smem + OFF_S2 + (c * KC + jh) * 4);
        const float4* epp = (const float4*)(smem + OFF_EP + (c * KC + jh) * 4);
        const float4* enp = (const float4*)(smem + OFF_EN + (c * KC + jh) * 4);
        uint32_t v[16];
        #pragma unroll
        for (int u = 0; u < 8; u++) {
            const int4 a4 = ar[u];
            const float4 sv = s2p[u], ep = epp[u], en = enp[u];
            float w0 = (sv.x >= rc.x) ? rc.y * ep.x : rc.z * en.x; if (a4.x == 0) w0 = 0.f;
            float w1 = (sv.y >= rc.x) ? rc.y * ep.y : rc.z * en.y; if (a4.y == 0) w1 = 0.f;
            float w2 = (sv.z >= rc.x) ? rc.y * ep.z : rc.z * en.z; if (a4.z == 0) w2 = 0.f;
            float w3 = (sv.w >= rc.x) ? rc.y * ep.w : rc.z * en.w; if (a4.w == 0) w3 = 0.f;
            __half2 p0 = __floats2half2_rn(w0, w1), p1 = __floats2half2_rn(w2, w3);
            v[2 * u] = *(uint32_t*)&p0; v[2 * u + 1] = *(uint32_t*)&p1;
        }
        uint4* dst = (uint4*)(smem + OFF_A + s * A_STG + m * 144 + jh * 2);
        dst[0] = make_uint4(v[0], v[1], v[2], v[3]);
        dst[1] = make_uint4(v[4], v[5], v[6], v[7]);
        dst[2] = make_uint4(v[8], v[9], v[10], v[11]);
        dst[3] = make_uint4(v[12], v[13], v[14], v[15]);
    };

    // prologue gen of chunk 0
    CP_WAIT1();
    __syncthreads();
    gen(0);

    #pragma unroll 1
    for (int c = 0; c < NC; c++) {
        if (c + 2 < NC) { fill_adj(c + 2, c & 1); fill_B(c + 2, (c + 2) % 3); }
        CP_COMMIT();
        CP_WAIT1();          // adj(c+1), B(c+1) arrived (B(c) earlier)
        __syncthreads();     // publish A[c&1] from last iter's gen + cp.async arrivals

        if (c + 1 < NC) gen(c + 1);        // writes A[(c+1)&1]

        // mma chunk c (same barrier-free region as gen -> warps overlap phases)
        const uint32_t aB = aB0 + (c & 1) * A_STG;
        const uint32_t bB = sb + OFF_B + (c % 3) * B_STG + bOff;
        #pragma unroll
        for (int kk = 0; kk < 4; kk++) {
            uint32_t a[2][4];
            ldsm4(a[0], aB + kk * 32);
            ldsm4(a[1], aB + 16 * 144 + kk * 32);
            #pragma unroll
            for (int ng = 0; ng < 4; ng++) {
                uint32_t b[4];
                ldsm4(b, bB + ng * 16 * 144 + kk * 32);
                #pragma unroll
                for (int mi = 0; mi < 2; mi++) {
                    mma16816(acc[mi][2 * ng], a[mi], b);
                    mma16816(acc[mi][2 * ng + 1], a[mi], b + 2);
                }
            }
            if ((wid & 1) == 0) {
                mma16816(az[0], a[0], ones);
                mma16816(az[1], a[1], ones);
            }
        }
    }

    // epilogue
    const int quad = lane >> 2, qc = (lane & 3) * 2;
    #pragma unroll
    for (int mi = 0; mi < 2; mi++) {
        const int rg = row0 + r0 + mi * 16 + quad;
        #pragma unroll
        for (int nt = 0; nt < 8; nt++) {
            const int col = c0 + nt * 8 + qc;
            float* p = g_part[slice] + (size_t)rg * FOUT + col;
            *(float2*)p = make_float2(acc[mi][nt][0], acc[mi][nt][1]);
            *(float2*)(p + 8 * FOUT) = make_float2(acc[mi][nt][2], acc[mi][nt][3]);
        }
        if ((wid & 1) == 0 && (lane & 3) == 0) {
            g_Zpart[slice][rg] = az[mi][0];
            g_Zpart[slice][rg + 8] = az[mi][2];
        }
    }
}

// combine K-slices: out = elu((p0+p1)/(z0+z1))
__global__ void __launch_bounds__(256) k_final(float* __restrict__ out) {
    const int idx = blockIdx.x * 256 + threadIdx.x;
    const int row = idx >> 5, c4 = (idx & 31) * 4;
    const float4 p0 = *(const float4*)(g_part[0] + (size_t)row * FOUT + c4);
    const float4 p1 = *(const float4*)(g_part[1] + (size_t)row * FOUT + c4);
    const float inv = 1.0f / (g_Zpart[0][row] + g_Zpart[1][row]);
    float4 o; float v;
    v = (p0.x + p1.x) * inv; o.x = v > 0.f ? v : expm1f(v);
    v = (p0.y + p1.y) * inv; o.y = v > 0.f ? v : expm1f(v);
    v = (p0.z + p1.z) * inv; o.z = v > 0.f ? v : expm1f(v);
    v = (p0.w + p1.w) * inv; o.w = v > 0.f ? v : expm1f(v);
    *(float4*)(out + (size_t)row * FOUT + c4) = o;
}

extern "C" void kernel_launch(void* const* d_in, const int* in_sizes, int n_in,
                              void* d_out, int out_size) {
    const float* h   = (const float*)d_in[0];
    const int*   adj = (const int*)d_in[1];
    const float* W   = (const float*)d_in[2];
    const float* a1  = (const float*)d_in[3];
    const float* a2  = (const float*)d_in[4];
    float* out = (float*)d_out;

    cudaFuncSetAttribute(k_attn, cudaFuncAttributeMaxDynamicSharedMemorySize, SMEM_TOTAL);

    k_wh     <<<N / 32, 128>>>(h, W);
    k_s12    <<<N / 8, 256>>>(a1, a2);
    k_s2max  <<<1, 1024>>>();
    k_factors<<<N / 256, 256>>>();
    k_attn   <<<128, 256, SMEM_TOTAL>>>(adj);
    k_final  <<<N * FOUT / 1024, 256>>>(out);
}